// round 16
// baseline (speedup 1.0000x reference)
#include <cuda_runtime.h>

// dims
#define NW   8192
#define LMAX 16
#define WED  506
#define WHD  512
#define G4   2048   // 4*WHD
#define CED  6
#define CHD  6
#define TLS  64

#define WBLK 64     // LSTM blocks
#define NGW  84     // GEMM worker blocks
#define NCH  128    // word chunks (8192/64)
#define NTIL (NCH * 32)   // 64x64 tiles: 128 bm x 32 bn

// ---------------- device scratch (no allocations allowed) ----------------
__device__ float g_hchar[NW * CHD];
__device__ float g_xp[(size_t)NW * G4];      // 64 MB
__device__ float g_hs[(size_t)NW * WHD];     // 16 MB
__device__ unsigned long long g_hbuf[2 * WHD];   // tagged h, parity double buffer
__device__ int g_cnt[NCH];                   // per-chunk tile counters

__device__ __forceinline__ float sigm(float x)  { return 1.f / (1.f + __expf(-x)); }
__device__ __forceinline__ float tanh_(float x) { return 2.f / (1.f + __expf(-2.f * x)) - 1.f; }

// ---------------- init: reset tag buffers + chunk counters ----------------
__global__ void init_kernel() {
    int i = blockIdx.x * blockDim.x + threadIdx.x;
    if (i < 2 * WHD) g_hbuf[i] = 0ull;   // tag=0, value=0.0f (h_0 = 0)
    if (i < NCH) g_cnt[i] = 0;
}

// ---------------- char-level LSTM: one thread per word ----------------
__global__ void char_lstm_kernel(const int* __restrict__ chars,
                                 const int* __restrict__ lens,
                                 const float* __restrict__ cemb,   // [128,6]
                                 const float* __restrict__ cWih,   // [24,6]
                                 const float* __restrict__ cWhh,   // [24,6]
                                 const float* __restrict__ cb) {   // [24]
    __shared__ float sE[128 * CED];
    __shared__ float sWi[24 * CED];
    __shared__ float sWh[24 * CHD];
    __shared__ float sB[24];
    int tid = threadIdx.x;
    for (int i = tid; i < 128 * CED; i += blockDim.x) sE[i] = cemb[i];
    if (tid < 144) { sWi[tid] = cWih[tid]; sWh[tid] = cWhh[tid]; }
    if (tid < 24) sB[tid] = cb[tid];
    __syncthreads();

    int n = blockIdx.x * blockDim.x + tid;
    if (n >= NW) return;
    int len = lens[n];
    float h[CHD], cs[CHD];
#pragma unroll
    for (int i = 0; i < CHD; i++) { h[i] = 0.f; cs[i] = 0.f; }

    for (int l = 0; l < len; l++) {
        int ch = chars[n * LMAX + l];
        const float* e = &sE[ch * CED];
        float x0 = e[0], x1 = e[1], x2 = e[2], x3 = e[3], x4 = e[4], x5 = e[5];
        float pre[24];
#pragma unroll
        for (int gi = 0; gi < 24; gi++) {
            const float* wi = &sWi[gi * CED];
            const float* wh = &sWh[gi * CHD];
            float p = sB[gi];
            p = fmaf(wi[0], x0, p); p = fmaf(wi[1], x1, p); p = fmaf(wi[2], x2, p);
            p = fmaf(wi[3], x3, p); p = fmaf(wi[4], x4, p); p = fmaf(wi[5], x5, p);
            p = fmaf(wh[0], h[0], p); p = fmaf(wh[1], h[1], p); p = fmaf(wh[2], h[2], p);
            p = fmaf(wh[3], h[3], p); p = fmaf(wh[4], h[4], p); p = fmaf(wh[5], h[5], p);
            pre[gi] = p;
        }
#pragma unroll
        for (int hd = 0; hd < CHD; hd++) {
            float ig = sigm(pre[hd]);
            float fg = sigm(pre[CHD + hd]);
            float gg = tanh_(pre[2 * CHD + hd]);
            float og = sigm(pre[3 * CHD + hd]);
            cs[hd] = fg * cs[hd] + ig * gg;
            h[hd]  = og * tanh_(cs[hd]);
        }
    }
#pragma unroll
    for (int hd = 0; hd < CHD; hd++) g_hchar[n * CHD + hd] = h[hd];
}

// ---------------- fused persistent kernel: LSTM (blocks 0..63) + GEMM ------
// LSTM path = R10 champion, byte-identical except the xp prefetch is gated on
// per-chunk readiness (acquire load of g_cnt).
// GEMM path (blocks 64..147): tiles bm-major so early words finish first;
// per tile: store xp, __threadfence, __syncthreads, atomicAdd(g_cnt[bm]).
#define WTHR 512
#define HPOS(c) ((c) + 4 * ((c) >> 4))
__global__ void __launch_bounds__(WTHR, 1)
fused_kernel(const float* __restrict__ Whh,     // [2048,512]
             const int* __restrict__ words,
             const float* __restrict__ wemb,    // [50000,506]
             const float* __restrict__ Wih,     // [2048,512]
             const float* __restrict__ wb) {    // [2048]
    // --- shared memory (union-sized by compiler: both declared) ---
    __shared__ __align__(16) float h_s[HPOS(WHD - 1) + 1 + 4];  // LSTM
    __shared__ __align__(16) float rs[32];                      // LSTM
    __shared__ float As[32][68];                                // GEMM
    __shared__ float Bs[32][68];                                // GEMM
    __shared__ int widx[64];                                    // GEMM

    int t = threadIdx.x;

    if (blockIdx.x >= WBLK) {
        // ================= GEMM worker path =================
        int wkr = blockIdx.x - WBLK;
        int tx = t & 15, ty = t >> 4;        // ty 0..31
        int lm = t & 63, lkg = (t >> 6) * 4; // k-line group

        for (int T = wkr; T < NTIL; T += NGW) {
            int bm = T >> 5, bn = T & 31;
            if (t < 64) widx[t] = words[bm * 64 + t];
            __syncthreads();

            float acc[2][4];
#pragma unroll
            for (int i = 0; i < 2; i++)
#pragma unroll
                for (int j = 0; j < 4; j++) acc[i][j] = 0.f;

            int m_g = bm * 64 + lm;
            const float* arow = wemb + (size_t)widx[lm] * WED;
            const float* brow = Wih + (size_t)(bn * 64 + lm) * WHD;

            for (int k0 = 0; k0 < WHD; k0 += 32) {
#pragma unroll
                for (int q = 0; q < 4; q++) {
                    int k = k0 + lkg + q;
                    float v = (k < WED) ? arow[k]
                                        : g_hchar[m_g * CHD + (k - WED)];
                    As[lkg + q][lm] = v;
                    Bs[lkg + q][lm] = brow[k];
                }
                __syncthreads();
#pragma unroll
                for (int k = 0; k < 32; k++) {
                    float2 a = *(const float2*)&As[k][ty * 2];
                    float4 bv = *(const float4*)&Bs[k][tx * 4];
                    acc[0][0] = fmaf(a.x, bv.x, acc[0][0]);
                    acc[0][1] = fmaf(a.x, bv.y, acc[0][1]);
                    acc[0][2] = fmaf(a.x, bv.z, acc[0][2]);
                    acc[0][3] = fmaf(a.x, bv.w, acc[0][3]);
                    acc[1][0] = fmaf(a.y, bv.x, acc[1][0]);
                    acc[1][1] = fmaf(a.y, bv.y, acc[1][1]);
                    acc[1][2] = fmaf(a.y, bv.z, acc[1][2]);
                    acc[1][3] = fmaf(a.y, bv.w, acc[1][3]);
                }
                __syncthreads();
            }
#pragma unroll
            for (int i = 0; i < 2; i++) {
                int m = bm * 64 + ty * 2 + i;
#pragma unroll
                for (int j = 0; j < 4; j++) {
                    int n = bn * 64 + tx * 4 + j;
                    g_xp[(size_t)m * G4 + n] = acc[i][j] + wb[n];
                }
            }
            __threadfence();     // make this thread's xp stores visible
            __syncthreads();     // all threads' stores fenced
            if (t == 0) atomicAdd(&g_cnt[bm], 1);
        }
        return;
    }

    // ================= LSTM path (R10 champion + chunk gate) =================
    int b = blockIdx.x;
    int wpi = t >> 5, l = t & 31;
    int r0 = 2 * wpi, r1 = r0 + 1;
    int row0 = (r0 & 3) * WHD + 8 * b + (r0 >> 2);
    int row1 = (r1 & 3) * WHD + 8 * b + (r1 >> 2);

    // weights: 16 cols [16l..16l+15] for each of the 2 rows
    float w0[16], w1[16];
#pragma unroll
    for (int k = 0; k < 16; k++) {
        w0[k] = Whh[(size_t)row0 * WHD + 16 * l + k];
        w1[k] = Whh[(size_t)row1 * WHD + 16 * l + k];
    }

    float cst = 0.f;  // cell state (threads 0..7: unit 8b+t)

    // xp prefetch: lanes 0/1 carry xp for row0/row1, gated on chunk readiness
    int myrow = (l == 0) ? row0 : row1;
    float x_cur = 0.f, x_nxt = 0.f;
    int wm = -1;  // highest chunk known ready (per-thread watermark)
    if (l < 2) {
        // wait for chunk 0
        int c;
        do {
            asm volatile("ld.acquire.gpu.global.b32 %0, [%1];"
                         : "=r"(c) : "l"(&g_cnt[0]));
        } while (c < 32);
        wm = 0;
        x_cur = __ldcg(&g_xp[myrow]);
    }

    for (int step = 1; step <= NW; ++step) {
        if (l < 2 && step < NW) {
            int chn = step >> 6;
            if (chn > wm) {
                int c;
                do {
                    asm volatile("ld.acquire.gpu.global.b32 %0, [%1];"
                                 : "=r"(c) : "l"(&g_cnt[chn]));
                } while (c < 32);
                wm = chn;
            }
            x_nxt = __ldcg(&g_xp[(size_t)step * G4 + myrow]);
        }

        // ---- poll: t<128 each owns one 32B sector of g_hbuf ----
        if (t < 128) {
            unsigned long long tg = (unsigned long long)(step - 1);
            const unsigned long long* src =
                g_hbuf + ((step - 1) & 1) * WHD + 4 * t;
            unsigned long long v0, v1, v2, v3;
            do {
                asm volatile("ld.volatile.global.v2.u64 {%0,%1}, [%2];"
                             : "=l"(v0), "=l"(v1) : "l"(src));
                asm volatile("ld.volatile.global.v2.u64 {%0,%1}, [%2+16];"
                             : "=l"(v2), "=l"(v3) : "l"(src));
            } while (((v0 >> 32) != tg) | ((v1 >> 32) != tg) |
                     ((v2 >> 32) != tg) | ((v3 >> 32) != tg));
            float4 hv = make_float4(__uint_as_float((unsigned)v0),
                                    __uint_as_float((unsigned)v1),
                                    __uint_as_float((unsigned)v2),
                                    __uint_as_float((unsigned)v3));
            // cols 4t..4t+3 stay inside one 16-group: aligned float4 store
            *(float4*)&h_s[HPOS(4 * t)] = hv;
        }
        __syncthreads();   // S1: h(step-1) staged

        // ---- matvec: 4x LDS.128 (conflict-free) + 32 FMA, 2 rows/thread ----
        float a0 = 0.f, a1 = 0.f, a2 = 0.f, a3 = 0.f;
#pragma unroll
        for (int q = 0; q < 4; q++) {
            float4 h4 = *(const float4*)&h_s[20 * l + 4 * q];
            if (q & 1) {
                a1 = fmaf(w0[4 * q + 0], h4.x, a1); a1 = fmaf(w0[4 * q + 1], h4.y, a1);
                a1 = fmaf(w0[4 * q + 2], h4.z, a1); a1 = fmaf(w0[4 * q + 3], h4.w, a1);
                a3 = fmaf(w1[4 * q + 0], h4.x, a3); a3 = fmaf(w1[4 * q + 1], h4.y, a3);
                a3 = fmaf(w1[4 * q + 2], h4.z, a3); a3 = fmaf(w1[4 * q + 3], h4.w, a3);
            } else {
                a0 = fmaf(w0[4 * q + 0], h4.x, a0); a0 = fmaf(w0[4 * q + 1], h4.y, a0);
                a0 = fmaf(w0[4 * q + 2], h4.z, a0); a0 = fmaf(w0[4 * q + 3], h4.w, a0);
                a2 = fmaf(w1[4 * q + 0], h4.x, a2); a2 = fmaf(w1[4 * q + 1], h4.y, a2);
                a2 = fmaf(w1[4 * q + 2], h4.z, a2); a2 = fmaf(w1[4 * q + 3], h4.w, a2);
            }
        }
        float s0 = a0 + a1, s1 = a2 + a3;
#pragma unroll
        for (int d = 16; d >= 1; d >>= 1) {
            s0 += __shfl_xor_sync(0xffffffffu, s0, d);
            s1 += __shfl_xor_sync(0xffffffffu, s1, d);
        }
        if (l < 2) rs[r0 + l] = ((l == 0) ? s0 : s1) + x_cur;
        __syncthreads();   // S2: rs ready

        // ---- gate tail: warp 0, 32 lanes = 8 units x 4 gates ----
        if (t < 32) {
            float pre = rs[t];            // rs[4u + k]: gate k of unit u
            int k = t & 3;
            float nl = (k == 2) ? tanh_(pre) : sigm(pre);
            int base = t & ~3;
            float gi = __shfl_sync(0xffffffffu, nl, base + 0);
            float gf = __shfl_sync(0xffffffffu, nl, base + 1);
            float gv = __shfl_sync(0xffffffffu, nl, base + 2);
            float go = __shfl_sync(0xffffffffu, nl, base + 3);
            if (k == 0) {
                cst = gf * cst + gi * gv;
                float hval = go * tanh_(cst);
                int jj = 8 * b + (t >> 2);
                // publish ASAP: 8 lanes -> 64B coalesced tagged store
                ((volatile unsigned long long*)g_hbuf)[(step & 1) * WHD + jj] =
                    (((unsigned long long)step) << 32) |
                    (unsigned long long)__float_as_uint(hval);
                g_hs[(size_t)(step - 1) * WHD + jj] = hval;
            }
        }
        if (l < 2) x_cur = x_nxt;
        // hazards identical to R10 champion: all h_s reads precede S2;
        // pollers rewrite h_s only after S2(step). rs rewrites after next S1.
        // g_hbuf overwrite induction unchanged. xp reads additionally ordered
        // after g_cnt acquire load (GEMM side: stores -> fence -> atomicAdd).
    }
}

// ---------------- logits + log_softmax: one block (64 threads) per row ----
__global__ void logits_kernel(const float* __restrict__ outW,  // [64,512]
                              const float* __restrict__ outb,  // [64]
                              float* __restrict__ out) {       // [8192,64]
    int row = blockIdx.x;
    int t = threadIdx.x;          // 0..63
    __shared__ float h_s[WHD];
    __shared__ float sm_[2], ss_[2];

    for (int i = t; i < WHD; i += 64) h_s[i] = g_hs[(size_t)row * WHD + i];
    __syncthreads();

    float acc = outb[t];
    const float4* w4 = (const float4*)(outW + (size_t)t * WHD);
#pragma unroll 8
    for (int k4 = 0; k4 < WHD / 4; k4++) {
        float4 wv = __ldg(&w4[k4]);
        acc = fmaf(wv.x, h_s[k4 * 4 + 0], acc);
        acc = fmaf(wv.y, h_s[k4 * 4 + 1], acc);
        acc = fmaf(wv.z, h_s[k4 * 4 + 2], acc);
        acc = fmaf(wv.w, h_s[k4 * 4 + 3], acc);
    }
    int lane = t & 31, wp = t >> 5;
    float m = acc;
#pragma unroll
    for (int d = 16; d >= 1; d >>= 1) m = fmaxf(m, __shfl_xor_sync(0xffffffffu, m, d));
    if (lane == 0) sm_[wp] = m;
    __syncthreads();
    m = fmaxf(sm_[0], sm_[1]);

    float e = __expf(acc - m);
    float s = e;
#pragma unroll
    for (int d = 16; d >= 1; d >>= 1) s += __shfl_xor_sync(0xffffffffu, s, d);
    if (lane == 0) ss_[wp] = s;
    __syncthreads();
    s = ss_[0] + ss_[1];

    out[(size_t)row * TLS + t] = acc - m - __logf(s);
}

// ---------------- launch ----------------
extern "C" void kernel_launch(void* const* d_in, const int* in_sizes, int n_in,
                              void* d_out, int out_size) {
    const int*   words = (const int*)d_in[0];
    const int*   chars = (const int*)d_in[1];
    const int*   lens  = (const int*)d_in[2];
    const float* wemb  = (const float*)d_in[3];
    const float* cemb  = (const float*)d_in[4];
    const float* cWih  = (const float*)d_in[5];
    const float* cWhh  = (const float*)d_in[6];
    const float* cb    = (const float*)d_in[7];
    const float* wWih  = (const float*)d_in[8];
    const float* wWhh  = (const float*)d_in[9];
    const float* wb    = (const float*)d_in[10];
    const float* outW  = (const float*)d_in[11];
    const float* outb  = (const float*)d_in[12];
    float* out = (float*)d_out;

    init_kernel<<<4, 256>>>();
    char_lstm_kernel<<<NW / 256, 256>>>(chars, lens, cemb, cWih, cWhh, cb);
    fused_kernel<<<WBLK + NGW, WTHR>>>(wWhh, words, wemb, wWih, wb);
    logits_kernel<<<NW, 64>>>(outW, outb, out);
}

// round 17
// speedup vs baseline: 1.2517x; 1.2517x over previous
#include <cuda_runtime.h>

// dims
#define NW   8192
#define LMAX 16
#define WED  506
#define WHD  512
#define G4   2048   // 4*WHD
#define CED  6
#define CHD  6
#define TLS  64

// ---------------- device scratch (no allocations allowed) ----------------
__device__ float g_hchar[NW * CHD];
__device__ float g_xp[(size_t)NW * G4];      // 64 MB
__device__ float g_hs[(size_t)NW * WHD];     // 16 MB
__device__ unsigned long long g_hbuf[2 * WHD];   // tagged h, parity double buffer

__device__ __forceinline__ float sigm(float x)  { return 1.f / (1.f + __expf(-x)); }
__device__ __forceinline__ float tanh_(float x) { return 2.f / (1.f + __expf(-2.f * x)) - 1.f; }

// ---------------- init: reset tag buffers (tags monotone within a run) ----
__global__ void init_kernel() {
    int i = blockIdx.x * blockDim.x + threadIdx.x;
    if (i < 2 * WHD) g_hbuf[i] = 0ull;   // tag=0, value=0.0f (h_0 = 0)
}

// ---------------- char-level LSTM: one thread per word ----------------
__global__ void char_lstm_kernel(const int* __restrict__ chars,
                                 const int* __restrict__ lens,
                                 const float* __restrict__ cemb,   // [128,6]
                                 const float* __restrict__ cWih,   // [24,6]
                                 const float* __restrict__ cWhh,   // [24,6]
                                 const float* __restrict__ cb) {   // [24]
    __shared__ float sE[128 * CED];
    __shared__ float sWi[24 * CED];
    __shared__ float sWh[24 * CHD];
    __shared__ float sB[24];
    int tid = threadIdx.x;
    for (int i = tid; i < 128 * CED; i += blockDim.x) sE[i] = cemb[i];
    if (tid < 144) { sWi[tid] = cWih[tid]; sWh[tid] = cWhh[tid]; }
    if (tid < 24) sB[tid] = cb[tid];
    __syncthreads();

    int n = blockIdx.x * blockDim.x + tid;
    if (n >= NW) return;
    int len = lens[n];
    float h[CHD], cs[CHD];
#pragma unroll
    for (int i = 0; i < CHD; i++) { h[i] = 0.f; cs[i] = 0.f; }

    for (int l = 0; l < len; l++) {
        int ch = chars[n * LMAX + l];
        const float* e = &sE[ch * CED];
        float x0 = e[0], x1 = e[1], x2 = e[2], x3 = e[3], x4 = e[4], x5 = e[5];
        float pre[24];
#pragma unroll
        for (int gi = 0; gi < 24; gi++) {
            const float* wi = &sWi[gi * CED];
            const float* wh = &sWh[gi * CHD];
            float p = sB[gi];
            p = fmaf(wi[0], x0, p); p = fmaf(wi[1], x1, p); p = fmaf(wi[2], x2, p);
            p = fmaf(wi[3], x3, p); p = fmaf(wi[4], x4, p); p = fmaf(wi[5], x5, p);
            p = fmaf(wh[0], h[0], p); p = fmaf(wh[1], h[1], p); p = fmaf(wh[2], h[2], p);
            p = fmaf(wh[3], h[3], p); p = fmaf(wh[4], h[4], p); p = fmaf(wh[5], h[5], p);
            pre[gi] = p;
        }
#pragma unroll
        for (int hd = 0; hd < CHD; hd++) {
            float ig = sigm(pre[hd]);
            float fg = sigm(pre[CHD + hd]);
            float gg = tanh_(pre[2 * CHD + hd]);
            float og = sigm(pre[3 * CHD + hd]);
            cs[hd] = fg * cs[hd] + ig * gg;
            h[hd]  = og * tanh_(cs[hd]);
        }
    }
#pragma unroll
    for (int hd = 0; hd < CHD; hd++) g_hchar[n * CHD + hd] = h[hd];
}

// ---------------- xp GEMM: xp[n, r] = dot(x[n,:], Wih[r,:]) + b[r] ----------
#define BM 64
#define BN 64
#define BK 32
__global__ void xp_gemm_kernel(const int* __restrict__ words,
                               const float* __restrict__ wemb,   // [50000,506]
                               const float* __restrict__ Wih,    // [2048,512]
                               const float* __restrict__ wb) {   // [2048]
    __shared__ float As[BK][BM + 4];
    __shared__ float Bs[BK][BN + 4];
    __shared__ int widx[BM];

    int bn = blockIdx.x;
    int bm = blockIdx.y;
    int tid = threadIdx.x;

    if (tid < BM) widx[tid] = words[bm * BM + tid];
    __syncthreads();

    int tx = tid % 16, ty = tid / 16;
    int lm = tid % 64;
    int lk = (tid / 64) * 8;

    float acc[4][4];
#pragma unroll
    for (int i = 0; i < 4; i++)
#pragma unroll
        for (int j = 0; j < 4; j++) acc[i][j] = 0.f;

    int m_g = bm * BM + lm;
    const float* arow = wemb + (size_t)widx[lm] * WED;
    const float* brow = Wih + (size_t)(bn * BN + lm) * WHD;

    for (int k0 = 0; k0 < WHD; k0 += BK) {
#pragma unroll
        for (int q = 0; q < 8; q++) {
            int k = k0 + lk + q;
            float v = (k < WED) ? arow[k] : g_hchar[m_g * CHD + (k - WED)];
            As[lk + q][lm] = v;
            Bs[lk + q][lm] = brow[k];
        }
        __syncthreads();
#pragma unroll
        for (int k = 0; k < BK; k++) {
            float4 a = *(const float4*)&As[k][ty * 4];
            float4 b = *(const float4*)&Bs[k][tx * 4];
            acc[0][0] = fmaf(a.x, b.x, acc[0][0]); acc[0][1] = fmaf(a.x, b.y, acc[0][1]);
            acc[0][2] = fmaf(a.x, b.z, acc[0][2]); acc[0][3] = fmaf(a.x, b.w, acc[0][3]);
            acc[1][0] = fmaf(a.y, b.x, acc[1][0]); acc[1][1] = fmaf(a.y, b.y, acc[1][1]);
            acc[1][2] = fmaf(a.y, b.z, acc[1][2]); acc[1][3] = fmaf(a.y, b.w, acc[1][3]);
            acc[2][0] = fmaf(a.z, b.x, acc[2][0]); acc[2][1] = fmaf(a.z, b.y, acc[2][1]);
            acc[2][2] = fmaf(a.z, b.z, acc[2][2]); acc[2][3] = fmaf(a.z, b.w, acc[2][3]);
            acc[3][0] = fmaf(a.w, b.x, acc[3][0]); acc[3][1] = fmaf(a.w, b.y, acc[3][1]);
            acc[3][2] = fmaf(a.w, b.z, acc[3][2]); acc[3][3] = fmaf(a.w, b.w, acc[3][3]);
        }
        __syncthreads();
    }
#pragma unroll
    for (int i = 0; i < 4; i++) {
        int m = bm * BM + ty * 4 + i;
#pragma unroll
        for (int j = 0; j < 4; j++) {
            int n = bn * BN + tx * 4 + j;
            g_xp[(size_t)m * G4 + n] = acc[i][j] + wb[n];
        }
    }
}

// ---------------- persistent word LSTM (R10 champion, unchanged) -----------
// 64 blocks x 512 threads, co-resident. Block b owns units 8b..8b+7 (32 gate
// rows). Warp w (0..15) owns rows {2w, 2w+1}; lane l covers cols
// [16l, 16l+16) for BOTH rows (2x h reuse per load).
// h_s padded layout pos(c)=c+4*(c>>4): conflict-free LDS.128.
// Poll: t<128 pull tagged u64 sectors of g_hbuf (parity double buffer).
// S1/S2 barriers, warp-0 parallel gate tail, 8-lane 64B coalesced publish.
#define WBLK 64
#define WTHR 512
#define HPOS(c) ((c) + 4 * ((c) >> 4))
__global__ void __launch_bounds__(WTHR, 1)
word_lstm_kernel(const float* __restrict__ Whh) {  // [2048,512]
    int b = blockIdx.x, t = threadIdx.x;
    int wpi = t >> 5, l = t & 31;
    int r0 = 2 * wpi, r1 = r0 + 1;
    int row0 = (r0 & 3) * WHD + 8 * b + (r0 >> 2);
    int row1 = (r1 & 3) * WHD + 8 * b + (r1 >> 2);

    // weights: 16 cols [16l..16l+15] for each of the 2 rows
    float w0[16], w1[16];
#pragma unroll
    for (int k = 0; k < 16; k++) {
        w0[k] = Whh[(size_t)row0 * WHD + 16 * l + k];
        w1[k] = Whh[(size_t)row1 * WHD + 16 * l + k];
    }

    __shared__ __align__(16) float h_s[HPOS(WHD - 1) + 1 + 4];  // padded
    __shared__ float rs[32];

    float cst = 0.f;  // cell state (k==0 lanes of warp 0)

    // xp prefetch: lanes 0/1 carry xp for row0/row1
    int myrow = (l == 0) ? row0 : row1;
    float x_cur = 0.f, x_nxt = 0.f;
    if (l < 2) x_cur = __ldcg(&g_xp[myrow]);

    for (int step = 1; step <= NW; ++step) {
        if (l < 2 && step < NW) x_nxt = __ldcg(&g_xp[(size_t)step * G4 + myrow]);

        // ---- poll: t<128 each owns one 32B sector of g_hbuf ----
        if (t < 128) {
            unsigned long long tg = (unsigned long long)(step - 1);
            const unsigned long long* src =
                g_hbuf + ((step - 1) & 1) * WHD + 4 * t;
            unsigned long long v0, v1, v2, v3;
            do {
                asm volatile("ld.volatile.global.v2.u64 {%0,%1}, [%2];"
                             : "=l"(v0), "=l"(v1) : "l"(src));
                asm volatile("ld.volatile.global.v2.u64 {%0,%1}, [%2+16];"
                             : "=l"(v2), "=l"(v3) : "l"(src));
            } while (((v0 >> 32) != tg) | ((v1 >> 32) != tg) |
                     ((v2 >> 32) != tg) | ((v3 >> 32) != tg));
            float4 hv = make_float4(__uint_as_float((unsigned)v0),
                                    __uint_as_float((unsigned)v1),
                                    __uint_as_float((unsigned)v2),
                                    __uint_as_float((unsigned)v3));
            // cols 4t..4t+3 stay inside one 16-group: aligned float4 store
            *(float4*)&h_s[HPOS(4 * t)] = hv;
        }
        __syncthreads();   // S1: h(step-1) staged

        // ---- matvec: 4x LDS.128 (conflict-free) + 32 FMA, 2 rows/thread ----
        float a0 = 0.f, a1 = 0.f, a2 = 0.f, a3 = 0.f;
#pragma unroll
        for (int q = 0; q < 4; q++) {
            float4 h4 = *(const float4*)&h_s[20 * l + 4 * q];
            if (q & 1) {
                a1 = fmaf(w0[4 * q + 0], h4.x, a1); a1 = fmaf(w0[4 * q + 1], h4.y, a1);
                a1 = fmaf(w0[4 * q + 2], h4.z, a1); a1 = fmaf(w0[4 * q + 3], h4.w, a1);
                a3 = fmaf(w1[4 * q + 0], h4.x, a3); a3 = fmaf(w1[4 * q + 1], h4.y, a3);
                a3 = fmaf(w1[4 * q + 2], h4.z, a3); a3 = fmaf(w1[4 * q + 3], h4.w, a3);
            } else {
                a0 = fmaf(w0[4 * q + 0], h4.x, a0); a0 = fmaf(w0[4 * q + 1], h4.y, a0);
                a0 = fmaf(w0[4 * q + 2], h4.z, a0); a0 = fmaf(w0[4 * q + 3], h4.w, a0);
                a2 = fmaf(w1[4 * q + 0], h4.x, a2); a2 = fmaf(w1[4 * q + 1], h4.y, a2);
                a2 = fmaf(w1[4 * q + 2], h4.z, a2); a2 = fmaf(w1[4 * q + 3], h4.w, a2);
            }
        }
        float s0 = a0 + a1, s1 = a2 + a3;
#pragma unroll
        for (int d = 16; d >= 1; d >>= 1) {
            s0 += __shfl_xor_sync(0xffffffffu, s0, d);
            s1 += __shfl_xor_sync(0xffffffffu, s1, d);
        }
        if (l < 2) rs[r0 + l] = ((l == 0) ? s0 : s1) + x_cur;
        __syncthreads();   // S2: rs ready

        // ---- gate tail: warp 0, 32 lanes = 8 units x 4 gates ----
        if (t < 32) {
            float pre = rs[t];            // rs[4u + k]: gate k of unit u
            int k = t & 3;
            float nl = (k == 2) ? tanh_(pre) : sigm(pre);
            int base = t & ~3;
            float gi = __shfl_sync(0xffffffffu, nl, base + 0);
            float gf = __shfl_sync(0xffffffffu, nl, base + 1);
            float gv = __shfl_sync(0xffffffffu, nl, base + 2);
            float go = __shfl_sync(0xffffffffu, nl, base + 3);
            if (k == 0) {
                cst = gf * cst + gi * gv;
                float hval = go * tanh_(cst);
                int jj = 8 * b + (t >> 2);
                // publish ASAP: 8 lanes -> 64B coalesced tagged store
                ((volatile unsigned long long*)g_hbuf)[(step & 1) * WHD + jj] =
                    (((unsigned long long)step) << 32) |
                    (unsigned long long)__float_as_uint(hval);
                g_hs[(size_t)(step - 1) * WHD + jj] = hval;
            }
        }
        if (l < 2) x_cur = x_nxt;
        // hazards (R7/R10-proven): all h_s reads precede S2; pollers rewrite
        // h_s only after passing S2(step). rs rewrites happen after next S1.
        // g_hbuf overwrite induction: publishing tag(step) follows local
        // S1(step), which required all blocks to have consumed tag step-2.
    }
}

// ---------------- logits + log_softmax: tiled GEMM, 64 rows/block ----------
// grid 128 blocks x 256 threads. Block bm computes rows [64bm, 64bm+64) x
// all 64 tag cols with smem-staged K-chunks (outW read once per block from
// L2, not per-row through L1). Softmax in-block: 4 threads/row x 16 cols.
__global__ void logits_kernel(const float* __restrict__ outW,  // [64,512]
                              const float* __restrict__ outb,  // [64]
                              float* __restrict__ out) {       // [8192,64]
    __shared__ float As[BK][BM + 4];
    __shared__ float Bs[BK][TLS + 4];
    __shared__ float ls[BM][TLS + 4];

    int bm = blockIdx.x;
    int t = threadIdx.x;
    int tx = t % 16, ty = t / 16;
    int lm = t % 64;
    int lk = (t / 64) * 8;

    float acc[4][4];
#pragma unroll
    for (int i = 0; i < 4; i++)
#pragma unroll
        for (int j = 0; j < 4; j++) acc[i][j] = 0.f;

    const float* arow = g_hs + (size_t)(bm * BM + lm) * WHD;
    const float* brow = outW + (size_t)lm * WHD;   // lm < 64 = tag col

    for (int k0 = 0; k0 < WHD; k0 += BK) {
#pragma unroll
        for (int q = 0; q < 8; q++) {
            int k = k0 + lk + q;
            As[lk + q][lm] = arow[k];
            Bs[lk + q][lm] = brow[k];
        }
        __syncthreads();
#pragma unroll
        for (int k = 0; k < BK; k++) {
            float4 a = *(const float4*)&As[k][ty * 4];
            float4 b = *(const float4*)&Bs[k][tx * 4];
            acc[0][0] = fmaf(a.x, b.x, acc[0][0]); acc[0][1] = fmaf(a.x, b.y, acc[0][1]);
            acc[0][2] = fmaf(a.x, b.z, acc[0][2]); acc[0][3] = fmaf(a.x, b.w, acc[0][3]);
            acc[1][0] = fmaf(a.y, b.x, acc[1][0]); acc[1][1] = fmaf(a.y, b.y, acc[1][1]);
            acc[1][2] = fmaf(a.y, b.z, acc[1][2]); acc[1][3] = fmaf(a.y, b.w, acc[1][3]);
            acc[2][0] = fmaf(a.z, b.x, acc[2][0]); acc[2][1] = fmaf(a.z, b.y, acc[2][1]);
            acc[2][2] = fmaf(a.z, b.z, acc[2][2]); acc[2][3] = fmaf(a.z, b.w, acc[2][3]);
            acc[3][0] = fmaf(a.w, b.x, acc[3][0]); acc[3][1] = fmaf(a.w, b.y, acc[3][1]);
            acc[3][2] = fmaf(a.w, b.z, acc[3][2]); acc[3][3] = fmaf(a.w, b.w, acc[3][3]);
        }
        __syncthreads();
    }

    // stage logits (+bias) into smem tile
#pragma unroll
    for (int i = 0; i < 4; i++)
#pragma unroll
        for (int j = 0; j < 4; j++)
            ls[ty * 4 + i][tx * 4 + j] = acc[i][j] + outb[tx * 4 + j];
    __syncthreads();

    // softmax: 4 threads per row, 16 cols each; reduce via 2 xor-shfls
    int row = t >> 2, seg = t & 3;
    const float* lr = &ls[row][seg * 16];
    float m = lr[0];
#pragma unroll
    for (int c = 1; c < 16; c++) m = fmaxf(m, lr[c]);
    m = fmaxf(m, __shfl_xor_sync(0xffffffffu, m, 1));
    m = fmaxf(m, __shfl_xor_sync(0xffffffffu, m, 2));

    float s = 0.f;
#pragma unroll
    for (int c = 0; c < 16; c++) s += __expf(lr[c] - m);
    s += __shfl_xor_sync(0xffffffffu, s, 1);
    s += __shfl_xor_sync(0xffffffffu, s, 2);
    float lg = m + __logf(s);

    float* orow = out + (size_t)(bm * BM + row) * TLS + seg * 16;
#pragma unroll
    for (int c = 0; c < 16; c++) orow[c] = lr[c] - lg;
}

// ---------------- launch ----------------
extern "C" void kernel_launch(void* const* d_in, const int* in_sizes, int n_in,
                              void* d_out, int out_size) {
    const int*   words = (const int*)d_in[0];
    const int*   chars = (const int*)d_in[1];
    const int*   lens  = (const int*)d_in[2];
    const float* wemb  = (const float*)d_in[3];
    const float* cemb  = (const float*)d_in[4];
    const float* cWih  = (const float*)d_in[5];
    const float* cWhh  = (const float*)d_in[6];
    const float* cb    = (const float*)d_in[7];
    const float* wWih  = (const float*)d_in[8];
    const float* wWhh  = (const float*)d_in[9];
    const float* wb    = (const float*)d_in[10];
    const float* outW  = (const float*)d_in[11];
    const float* outb  = (const float*)d_in[12];
    float* out = (float*)d_out;

    init_kernel<<<4, 256>>>();
    char_lstm_kernel<<<NW / 256, 256>>>(chars, lens, cemb, cWih, cWhh, cb);
    {
        dim3 grid(G4 / BN, NW / BM);
        xp_gemm_kernel<<<grid, 256>>>(words, wemb, wWih, wb);
    }
    word_lstm_kernel<<<WBLK, WTHR>>>(wWhh);
    logits_kernel<<<NW / BM, 256>>>(outW, outb, out);
}